// round 9
// baseline (speedup 1.0000x reference)
#include <cuda_runtime.h>
#include <cuda_fp16.h>
#include <math.h>
#include <stdint.h>

#define NQ   512
#define NC   16
#define CS   64
#define HID  128
#define NB   2048
#define ROUNDS 4
#define GRID   148
#define THREADS 512

#define WST  272          // padded fp16 row stride in bytes (128 halfs + 8 pad)

// ---- smem offsets ----
#define OFF_TAB  0                          // 512*256   = 131072
#define OFF_W    131072                     // 128*272   = 34816
#define OFF_M    165888                     // 64*272    = 17408
#define OFF_BUF  183296                     // 2*4*16*64*2 = 16384 (double-buffered)
#define OFF_CE   199680                     // 4*16*32*8 = 16384 (also bucket scratch in GEMM phase)
#define OFF_AN2  216064                     // 256*8     = 2048
#define OFF_BIAS 218112                     // 512
#define OFF_CNT  218624                     // 2*64*4    = 512 (double-buffered)
#define SMEM_REQ 219136

__device__ float g_anorm[NC * NC];
__device__ __align__(16) __half g_embh[(NQ + 1) * HID];
__device__ __align__(16) __half g_Wh[HID * HID];   // W[o][h], fp16

typedef unsigned long long u64;

static __device__ __forceinline__ uint32_t smem_u32(const void* p) {
    uint32_t a;
    asm("{ .reg .u64 t; cvta.to.shared.u64 t, %1; cvt.u32.u64 %0, t; }" : "=r"(a) : "l"(p));
    return a;
}
static __device__ __forceinline__ u64 pack2(float lo, float hi) {
    u64 r; asm("mov.b64 %0, {%1, %2};" : "=l"(r) : "f"(lo), "f"(hi)); return r;
}
static __device__ __forceinline__ void ffma2(u64 &d, u64 a, u64 b) {
    asm("fma.rn.f32x2 %0, %1, %2, %0;" : "+l"(d) : "l"(a), "l"(b));
}
static __device__ __forceinline__ float2 unpack2(u64 v) {
    float x, y; asm("mov.b64 {%0, %1}, %2;" : "=f"(x), "=f"(y) : "l"(v));
    return make_float2(x, y);
}
static __device__ __forceinline__ void ldsm_x4(uint32_t* r, uint32_t addr) {
    asm volatile("ldmatrix.sync.aligned.m8n8.x4.shared.b16 {%0,%1,%2,%3}, [%4];"
        : "=r"(r[0]), "=r"(r[1]), "=r"(r[2]), "=r"(r[3]) : "r"(addr));
}
static __device__ __forceinline__ void mma16816(float* d, const uint32_t* a, const uint32_t* b) {
    asm volatile("mma.sync.aligned.m16n8k16.row.col.f32.f16.f16.f32 "
        "{%0,%1,%2,%3}, {%4,%5,%6,%7}, {%8,%9}, {%0,%1,%2,%3};"
        : "+f"(d[0]), "+f"(d[1]), "+f"(d[2]), "+f"(d[3])
        : "r"(a[0]), "r"(a[1]), "r"(a[2]), "r"(a[3]), "r"(b[0]), "r"(b[1]));
}

// ---------------- prep: anorm, fp16 table, fp16 W ----------------
__global__ void prep_kernel(const float* __restrict__ adj,
                            const float* __restrict__ W,
                            const float* __restrict__ qemb) {
    int t = threadIdx.x, b = blockIdx.x;
    if (b < 64) {
        int idx = b * 256 + t;                 // 16384 W entries
        g_Wh[idx] = __float2half(W[idx]);
    } else if (b == 64) {
        int i = t >> 4, j = t & 15;
        float di = 0.f, dj = 0.f;
#pragma unroll
        for (int r = 0; r < NC; r++) { di += adj[r * NC + i]; dj += adj[r * NC + j]; }
        di = di > 0.f ? rsqrtf(di) : 0.f;
        dj = dj > 0.f ? rsqrtf(dj) : 0.f;
        g_anorm[t] = adj[t] * di * dj;
    } else {
        int idx = (b - 65) * 256 + t;
        if (idx < (NQ + 1) * HID) g_embh[idx] = __float2half(qemb[idx]);
    }
}

// ---------------- fused: smem table -> match-bucket -> pool -> mix -> mma.sync GEMM ----------------
__global__ void __launch_bounds__(THREADS, 1)
enc_kernel(const int*   __restrict__ la,
           const float* __restrict__ bias,
           float*       __restrict__ out)
{
    extern __shared__ __align__(16) char smem[];
    const uint32_t sb = smem_u32(smem);

    const int tid  = threadIdx.x;
    const int lane = tid & 31;
    const int w    = tid >> 5;
    const int blk  = blockIdx.x;

    // 2048 = 124*14 + 24*13
    const int b0     = blk * 13 + (blk < 124 ? blk : 124);
    const int nbatch = 13 + (blk < 124 ? 1 : 0);

    unsigned short* s_buf  = (unsigned short*)(smem + OFF_BUF);  // [2][4][16][64]
    int*            s_cnt  = (int*)(smem + OFF_CNT);             // [2][4][16]
    u64*            s_an2  = (u64*)(smem + OFF_AN2);
    float*          s_bias = (float*)(smem + OFF_BIAS);

    const unsigned lt = (1u << lane) - 1u;

    // ---- phase 0: constants + table + W into smem; warps 0-3 bucket round 0 ----
    if (tid < 256) { float a = g_anorm[tid]; s_an2[tid] = pack2(a, a); }
    else if (tid < 384) s_bias[tid - 256] = bias[tid - 256];
    {
        const uint4* src = (const uint4*)g_embh;
        uint4* dst = (uint4*)(smem + OFF_TAB);
#pragma unroll
        for (int i = 0; i < 16; i++) dst[i * THREADS + tid] = src[i * THREADS + tid];
    }
    {
        const uint4* src = (const uint4*)g_Wh;
#pragma unroll
        for (int k = 0; k < 4; k++) {
            int idx = k * THREADS + tid;          // 2048 uint4
            int o = idx >> 4, seg = idx & 15;
            *(uint4*)(smem + OFF_W + o * WST + seg * 16) = src[idx];
        }
    }
    if (w < 4) {   // bucket round 0 into buffer 0 (round 0 always has 4 valid batches)
        int* cw = s_cnt + w * NC;
        if (lane < NC) cw[lane] = 0;
        __syncwarp();
        const int* lr = la + (size_t)(b0 + w) * NQ;
        unsigned short* bw = s_buf + w * NC * CS;
#pragma unroll
        for (int it = 0; it < 16; it++) {
            int a = __ldg(lr + it * 32 + lane);
            unsigned m = __match_any_sync(0xFFFFFFFFu, a);
            int rank = __popc(m & lt);
            int leader = __ffs((int)m) - 1;
            int base = 0;
            if (lane == leader) base = atomicAdd(&cw[a], __popc(m));
            base = __shfl_sync(0xFFFFFFFFu, base, leader);
            int pos = base + rank;
            if (pos < CS) bw[a * CS + pos] = (unsigned short)(it * 32 + lane);
        }
    }
    __syncthreads();

    for (int R = 0; R < ROUNDS; R++) {
        const int nb = min(4, nbatch - R * 4);   // active batches this round (>=1)
        const int cbuf = (R & 1);

        // ---- pool from smem table: warp -> (batch w>>2, cores (w&3)*4..+3) ----
        {
            const int bb = w >> 2;
            const int c0 = (w & 3) * 4;
            uint2* ce = (uint2*)(smem + OFF_CE);
#pragma unroll
            for (int cc = 0; cc < 4; cc++) {
                int c = c0 + cc;
                int cnt = s_cnt[cbuf * 64 + bb * NC + c];
                int n = cnt < CS ? cnt : CS;
                __half2 a0 = __half2half2(__ushort_as_half(
                                 (unsigned short)(cnt >= CS ? 0xFC00 : 0)));
                __half2 a1 = a0;
                const unsigned short* bq = &s_buf[cbuf * 4096 + (bb * NC + c) * CS];
                int i = 0;
                for (; i + 4 <= n; i += 4) {
                    u64 qq = *(const u64*)(bq + i);
                    uint32_t q0 = (uint32_t)(qq) & 0xFFFFu;
                    uint32_t q1 = (uint32_t)(qq >> 16) & 0xFFFFu;
                    uint32_t q2 = (uint32_t)(qq >> 32) & 0xFFFFu;
                    uint32_t q3 = (uint32_t)(qq >> 48) & 0xFFFFu;
                    uint2 r0 = *(const uint2*)(smem + OFF_TAB + q0 * 256u + lane * 8u);
                    uint2 r1 = *(const uint2*)(smem + OFF_TAB + q1 * 256u + lane * 8u);
                    uint2 r2 = *(const uint2*)(smem + OFF_TAB + q2 * 256u + lane * 8u);
                    uint2 r3 = *(const uint2*)(smem + OFF_TAB + q3 * 256u + lane * 8u);
                    a0 = __hmax2(a0, *(__half2*)&r0.x); a1 = __hmax2(a1, *(__half2*)&r0.y);
                    a0 = __hmax2(a0, *(__half2*)&r1.x); a1 = __hmax2(a1, *(__half2*)&r1.y);
                    a0 = __hmax2(a0, *(__half2*)&r2.x); a1 = __hmax2(a1, *(__half2*)&r2.y);
                    a0 = __hmax2(a0, *(__half2*)&r3.x); a1 = __hmax2(a1, *(__half2*)&r3.y);
                }
                for (; i < n; i++) {
                    uint32_t q = bq[i];
                    uint2 r0 = *(const uint2*)(smem + OFF_TAB + q * 256u + lane * 8u);
                    a0 = __hmax2(a0, *(__half2*)&r0.x); a1 = __hmax2(a1, *(__half2*)&r0.y);
                }
                uint2 st;
                st.x = *(uint32_t*)&a0; st.y = *(uint32_t*)&a1;
                ce[(bb * NC + c) * 32 + lane] = st;
            }
        }
        __syncthreads();

        // ---- mix: warp -> (batch w>>2, i-group w&3); lane owns 4 h-cols ----
        {
            const int bb = w >> 2, ig = w & 3;
            const uint2* cep = (const uint2*)(smem + OFF_CE) + (bb * NC) * 32 + lane;
            u64 mlo[4], mhi[4];
#pragma unroll
            for (int ii = 0; ii < 4; ii++) { mlo[ii] = 0ull; mhi[ii] = 0ull; }
#pragma unroll
            for (int j = 0; j < NC; j++) {
                uint2 cu = cep[j * 32];
                float2 flo = __half22float2(*(__half2*)&cu.x);
                float2 fhi = __half22float2(*(__half2*)&cu.y);
                u64 vlo = pack2(flo.x, flo.y);
                u64 vhi = pack2(fhi.x, fhi.y);
#pragma unroll
                for (int ii = 0; ii < 4; ii++) {
                    u64 ap = s_an2[(ig * 4 + ii) * NC + j];
                    ffma2(mlo[ii], vlo, ap);
                    ffma2(mhi[ii], vhi, ap);
                }
            }
#pragma unroll
            for (int ii = 0; ii < 4; ii++) {
                int r = bb * NC + ig * 4 + ii;     // 0..63
                float2 l = unpack2(mlo[ii]);
                float2 h = unpack2(mhi[ii]);
                __half2 h0 = __floats2half2_rn(l.x, l.y);
                __half2 h1 = __floats2half2_rn(h.x, h.y);
                uint2 st; st.x = *(uint32_t*)&h0; st.y = *(uint32_t*)&h1;
                *(uint2*)(smem + OFF_M + r * WST + lane * 8) = st;
            }
        }
        __syncthreads();

        // ---- GEMM phase (+ pipelined bucket of round R+1 on warps 0-3) ----
        {
            const int nr = R + 1;
            const bool haveB = (w < 4) && (nr < ROUNDS);
            const bool validB = haveB && (nr * 4 + w < nbatch);
            int* scr = (int*)(smem + OFF_CE) + (w * 16) * 32 + lane;  // ce region is dead now

            // prefetch next-round assignment row into smem scratch (hides LDG latency under GEMM)
            if (validB) {
                const int* lr = la + (size_t)(b0 + nr * 4 + w) * NQ;
#pragma unroll
                for (int it = 0; it < 16; it++)
                    scr[it * 32] = __ldg(lr + it * 32 + lane);
            }

            // GEMM: D[64,128] = M[64,128] x W[128,128]^T via mma.sync
            const int rt = w & 3;        // row tile = batch in round
            const int ct = w >> 2;       // col tile (32 cols)
            float d[4][4];
#pragma unroll
            for (int nt = 0; nt < 4; nt++)
#pragma unroll
                for (int k = 0; k < 4; k++) d[nt][k] = 0.f;

            const uint32_t aBase = sb + OFF_M
                + (uint32_t)(rt * 16 + (lane & 15)) * WST + (uint32_t)((lane >> 4) * 16);
            const uint32_t bBase0 = sb + OFF_W
                + (uint32_t)(ct * 32 + (lane & 7) + ((lane >> 4) * 8)) * WST
                + (uint32_t)(((lane >> 3) & 1) * 16);
            const uint32_t bBase1 = bBase0 + 16 * WST;

#pragma unroll
            for (int s = 0; s < 8; s++) {
                uint32_t a[4], b0r[4], b1r[4];
                ldsm_x4(a,   aBase  + s * 32);
                ldsm_x4(b0r, bBase0 + s * 32);
                ldsm_x4(b1r, bBase1 + s * 32);
                mma16816(d[0], a, b0r + 0);
                mma16816(d[1], a, b0r + 2);
                mma16816(d[2], a, b1r + 0);
                mma16816(d[3], a, b1r + 2);
            }

            // epilogue: bias + direct stores (guarded for partial rounds)
            if (rt < nb) {
                const int g = lane >> 2, t = lane & 3;
                float* ob = out + (size_t)(b0 + R * 4 + rt) * (NC * HID);
                float* o0 = ob + g * HID;
                float* o1 = ob + (g + 8) * HID;
#pragma unroll
                for (int nt = 0; nt < 4; nt++) {
                    int col = ct * 32 + nt * 8 + 2 * t;
                    float bv0 = s_bias[col], bv1 = s_bias[col + 1];
                    *(float2*)(o0 + col) = make_float2(d[nt][0] + bv0, d[nt][1] + bv1);
                    *(float2*)(o1 + col) = make_float2(d[nt][2] + bv0, d[nt][3] + bv1);
                }
            }

            // bucket round R+1 from scratch (exact qubit order via match+rank)
            if (haveB) {
                int* cw = s_cnt + (nr & 1) * 64 + w * NC;
                if (lane < NC) cw[lane] = 0;
                __syncwarp();
                if (validB) {
                    unsigned short* bw = s_buf + (nr & 1) * 4096 + w * NC * CS;
#pragma unroll
                    for (int it = 0; it < 16; it++) {
                        int a = scr[it * 32];
                        unsigned m = __match_any_sync(0xFFFFFFFFu, a);
                        int rank = __popc(m & lt);
                        int leader = __ffs((int)m) - 1;
                        int base = 0;
                        if (lane == leader) base = atomicAdd(&cw[a], __popc(m));
                        base = __shfl_sync(0xFFFFFFFFu, base, leader);
                        int pos = base + rank;
                        if (pos < CS) bw[a * CS + pos] = (unsigned short)(it * 32 + lane);
                    }
                }
            }
        }
        __syncthreads();
    }
}

extern "C" void kernel_launch(void* const* d_in, const int* in_sizes, int n_in,
                              void* d_out, int out_size) {
    const int*   la   = (const int*)  d_in[0];   // (2048, 512) int32
    const float* adj  = (const float*)d_in[1];   // (16, 16) f32
    const float* qemb = (const float*)d_in[2];   // (513, 128) f32
    const float* W    = (const float*)d_in[3];   // (128, 128) f32
    const float* bias = (const float*)d_in[4];   // (128,) f32
    float* out = (float*)d_out;                  // (2048, 16, 128) f32

    cudaFuncSetAttribute(enc_kernel, cudaFuncAttributeMaxDynamicSharedMemorySize, SMEM_REQ);
    prep_kernel<<<322, 256>>>(adj, W, qemb);
    enc_kernel<<<GRID, THREADS, SMEM_REQ>>>(la, bias, out);
}

// round 10
// speedup vs baseline: 1.3969x; 1.3969x over previous
#include <cuda_runtime.h>
#include <cuda_fp16.h>
#include <math.h>
#include <stdint.h>

#define NQ   512
#define NC   16
#define CS   64
#define HID  128
#define NB   2048
#define ROUNDS 2
#define BPRD   8          // batches per round
#define GRID   148
#define THREADS 512

#define WST  272          // padded fp16 row stride in bytes (128 halfs + 8 pad)

// ---- smem offsets ----
#define OFF_TAB  0                          // 512*256    = 131072
#define OFF_W    131072                     // 128*272    = 34816
#define OFF_M    165888                     // 128*272    = 34816 (ce lives here too)
#define OFF_BUF  200704                     // 8*16*64*2  = 16384
#define OFF_AN2  217088                     // 256*8      = 2048
#define OFF_BIAS 219136                     // 512
#define OFF_CNT  219648                     // 8*16*4     = 512
#define SMEM_REQ 220160

__device__ float g_anorm[NC * NC];
__device__ __align__(16) __half g_embh[(NQ + 1) * HID];
__device__ __align__(16) __half g_Wh[HID * HID];   // W[o][h], fp16

typedef unsigned long long u64;

static __device__ __forceinline__ uint32_t smem_u32(const void* p) {
    uint32_t a;
    asm("{ .reg .u64 t; cvta.to.shared.u64 t, %1; cvt.u32.u64 %0, t; }" : "=r"(a) : "l"(p));
    return a;
}
static __device__ __forceinline__ u64 pack2(float lo, float hi) {
    u64 r; asm("mov.b64 %0, {%1, %2};" : "=l"(r) : "f"(lo), "f"(hi)); return r;
}
static __device__ __forceinline__ void ffma2(u64 &d, u64 a, u64 b) {
    asm("fma.rn.f32x2 %0, %1, %2, %0;" : "+l"(d) : "l"(a), "l"(b));
}
static __device__ __forceinline__ float2 unpack2(u64 v) {
    float x, y; asm("mov.b64 {%0, %1}, %2;" : "=f"(x), "=f"(y) : "l"(v));
    return make_float2(x, y);
}
static __device__ __forceinline__ void ldsm_x4(uint32_t* r, uint32_t addr) {
    asm volatile("ldmatrix.sync.aligned.m8n8.x4.shared.b16 {%0,%1,%2,%3}, [%4];"
        : "=r"(r[0]), "=r"(r[1]), "=r"(r[2]), "=r"(r[3]) : "r"(addr));
}
static __device__ __forceinline__ void mma16816(float* d, const uint32_t* a, const uint32_t* b) {
    asm volatile("mma.sync.aligned.m16n8k16.row.col.f32.f16.f16.f32 "
        "{%0,%1,%2,%3}, {%4,%5,%6,%7}, {%8,%9}, {%0,%1,%2,%3};"
        : "+f"(d[0]), "+f"(d[1]), "+f"(d[2]), "+f"(d[3])
        : "r"(a[0]), "r"(a[1]), "r"(a[2]), "r"(a[3]), "r"(b[0]), "r"(b[1]));
}

// ---------------- prep: anorm, fp16 table, fp16 W ----------------
__global__ void prep_kernel(const float* __restrict__ adj,
                            const float* __restrict__ W,
                            const float* __restrict__ qemb) {
    int t = threadIdx.x, b = blockIdx.x;
    if (b < 64) {
        int idx = b * 256 + t;                 // 16384 W entries
        g_Wh[idx] = __float2half(W[idx]);
    } else if (b == 64) {
        int i = t >> 4, j = t & 15;
        float di = 0.f, dj = 0.f;
#pragma unroll
        for (int r = 0; r < NC; r++) { di += adj[r * NC + i]; dj += adj[r * NC + j]; }
        di = di > 0.f ? rsqrtf(di) : 0.f;
        dj = dj > 0.f ? rsqrtf(dj) : 0.f;
        g_anorm[t] = adj[t] * di * dj;
    } else {
        int idx = (b - 65) * 256 + t;
        if (idx < (NQ + 1) * HID) g_embh[idx] = __float2half(qemb[idx]);
    }
}

// bucket one batch (R7-proven: warp-local atomics + rare order-correct fallback)
static __device__ __forceinline__ void bucket_batch(
    const int* __restrict__ la, size_t batch, int wslot, int lane,
    unsigned short* s_buf, int* s_cnt)
{
    int* cw = s_cnt + wslot * NC;
    unsigned short* bw = s_buf + wslot * NC * CS;
    if (lane < NC) cw[lane] = 0;
    __syncwarp();
    const int4* ap = (const int4*)(la + batch * NQ);
    bool ovf = false;
#pragma unroll
    for (int it = 0; it < 4; it++) {
        int4 v = ap[it * 32 + lane];
        int q0 = (it * 32 + lane) * 4;
        int p;
        p = atomicAdd(&cw[v.x], 1); if (p < CS) bw[v.x * CS + p] = (unsigned short)(q0 + 0); else ovf = true;
        p = atomicAdd(&cw[v.y], 1); if (p < CS) bw[v.y * CS + p] = (unsigned short)(q0 + 1); else ovf = true;
        p = atomicAdd(&cw[v.z], 1); if (p < CS) bw[v.z * CS + p] = (unsigned short)(q0 + 2); else ovf = true;
        p = atomicAdd(&cw[v.w], 1); if (p < CS) bw[v.w * CS + p] = (unsigned short)(q0 + 3); else ovf = true;
    }
    if (__any_sync(0xFFFFFFFFu, ovf)) {
        if (lane == 0) {
            int cnt[NC];
#pragma unroll
            for (int c = 0; c < NC; c++) cnt[c] = 0;
            for (int q = 0; q < NQ; q++) {
                int c = la[batch * NQ + q];
                int p = cnt[c];
                if (p < CS) bw[c * CS + p] = (unsigned short)q;
                cnt[c] = p + 1;
            }
#pragma unroll
            for (int c = 0; c < NC; c++) cw[c] = cnt[c];
        }
        __syncwarp();
    }
}

// ---------------- fused: smem table -> bucket -> pool -> (bucket||mix) -> mma.sync GEMM ----------------
__global__ void __launch_bounds__(THREADS, 1)
enc_kernel(const int*   __restrict__ la,
           const float* __restrict__ bias,
           float*       __restrict__ out)
{
    extern __shared__ __align__(16) char smem[];
    const uint32_t sb = smem_u32(smem);

    const int tid  = threadIdx.x;
    const int lane = tid & 31;
    const int w    = tid >> 5;
    const int blk  = blockIdx.x;

    // 2048 = 124*14 + 24*13
    const int b0     = blk * 13 + (blk < 124 ? blk : 124);
    const int nbatch = 13 + (blk < 124 ? 1 : 0);

    unsigned short* s_buf  = (unsigned short*)(smem + OFF_BUF);  // [8][16][64]
    int*            s_cnt  = (int*)(smem + OFF_CNT);             // [8][16]
    u64*            s_an2  = (u64*)(smem + OFF_AN2);
    float*          s_bias = (float*)(smem + OFF_BIAS);

    // ---- prologue: warps 8-15 load constants/table/W; warps 0-7 bucket round 0 ----
    if (w >= 8) {
        const int t2 = tid - 256;   // 0..255
        { float a = g_anorm[t2]; s_an2[t2] = pack2(a, a); }
        if (t2 < 128) s_bias[t2] = bias[t2];
        const uint4* tsrc = (const uint4*)g_embh;
        uint4* tdst = (uint4*)(smem + OFF_TAB);
#pragma unroll
        for (int i = 0; i < 32; i++) tdst[i * 256 + t2] = tsrc[i * 256 + t2];
        const uint4* wsrc = (const uint4*)g_Wh;
#pragma unroll
        for (int k = 0; k < 8; k++) {
            int idx = k * 256 + t2;               // 2048 uint4
            int o = idx >> 4, seg = idx & 15;
            *(uint4*)(smem + OFF_W + o * WST + seg * 16) = wsrc[idx];
        }
    } else {
        bucket_batch(la, (size_t)(b0 + w), w, lane, s_buf, s_cnt);   // round 0: 8 valid batches
    }
    __syncthreads();

    for (int R = 0; R < ROUNDS; R++) {
        const int nb = min(BPRD, nbatch - R * BPRD);   // active batches this round

        // ---- pool: warp -> (batch w>>1, cores (w&1)*8..+7); ce -> M-tile rows ----
        {
            const int bb = w >> 1;
            if (bb < nb) {
                const int c0 = (w & 1) * 8;
#pragma unroll
                for (int cc = 0; cc < 8; cc++) {
                    int c = c0 + cc;
                    int cnt = s_cnt[bb * NC + c];
                    int n = cnt < CS ? cnt : CS;
                    __half2 a0 = __half2half2(__ushort_as_half(
                                     (unsigned short)(cnt >= CS ? 0xFC00 : 0)));
                    __half2 a1 = a0;
                    const unsigned short* bq = &s_buf[(bb * NC + c) * CS];
                    int i = 0;
                    for (; i + 4 <= n; i += 4) {
                        u64 qq = *(const u64*)(bq + i);
                        uint32_t q0 = (uint32_t)(qq) & 0xFFFFu;
                        uint32_t q1 = (uint32_t)(qq >> 16) & 0xFFFFu;
                        uint32_t q2 = (uint32_t)(qq >> 32) & 0xFFFFu;
                        uint32_t q3 = (uint32_t)(qq >> 48) & 0xFFFFu;
                        uint2 r0 = *(const uint2*)(smem + OFF_TAB + q0 * 256u + lane * 8u);
                        uint2 r1 = *(const uint2*)(smem + OFF_TAB + q1 * 256u + lane * 8u);
                        uint2 r2 = *(const uint2*)(smem + OFF_TAB + q2 * 256u + lane * 8u);
                        uint2 r3 = *(const uint2*)(smem + OFF_TAB + q3 * 256u + lane * 8u);
                        a0 = __hmax2(a0, *(__half2*)&r0.x); a1 = __hmax2(a1, *(__half2*)&r0.y);
                        a0 = __hmax2(a0, *(__half2*)&r1.x); a1 = __hmax2(a1, *(__half2*)&r1.y);
                        a0 = __hmax2(a0, *(__half2*)&r2.x); a1 = __hmax2(a1, *(__half2*)&r2.y);
                        a0 = __hmax2(a0, *(__half2*)&r3.x); a1 = __hmax2(a1, *(__half2*)&r3.y);
                    }
                    for (; i < n; i++) {
                        uint32_t q = bq[i];
                        uint2 r0 = *(const uint2*)(smem + OFF_TAB + q * 256u + lane * 8u);
                        a0 = __hmax2(a0, *(__half2*)&r0.x); a1 = __hmax2(a1, *(__half2*)&r0.y);
                    }
                    uint2 st;
                    st.x = *(uint32_t*)&a0; st.y = *(uint32_t*)&a1;
                    *(uint2*)(smem + OFF_M + (bb * NC + c) * WST + lane * 8) = st;
                }
            }
        }
        __syncthreads();

        // ---- parallel phase: warps 0-7 bucket round R+1; warps 8-15 mix (in-place) ----
        if (w < 8) {
            const int nxt = (R + 1) * BPRD + w;
            if (R + 1 < ROUNDS && nxt < nbatch)
                bucket_batch(la, (size_t)(b0 + nxt), w, lane, s_buf, s_cnt);
        } else {
            const int bb = w - 8;
            if (bb < nb) {
                // read all 16 ce rows of this batch into regs, then mix + overwrite in place
                uint2 v[NC];
#pragma unroll
                for (int j = 0; j < NC; j++)
                    v[j] = *(const uint2*)(smem + OFF_M + (bb * NC + j) * WST + lane * 8);
#pragma unroll
                for (int half = 0; half < 2; half++) {
                    u64 mlo[8], mhi[8];
#pragma unroll
                    for (int ii = 0; ii < 8; ii++) { mlo[ii] = 0ull; mhi[ii] = 0ull; }
#pragma unroll
                    for (int j = 0; j < NC; j++) {
                        float2 flo = __half22float2(*(__half2*)&v[j].x);
                        float2 fhi = __half22float2(*(__half2*)&v[j].y);
                        u64 vlo = pack2(flo.x, flo.y);
                        u64 vhi = pack2(fhi.x, fhi.y);
#pragma unroll
                        for (int ii = 0; ii < 8; ii++) {
                            u64 ap = s_an2[(half * 8 + ii) * NC + j];
                            ffma2(mlo[ii], vlo, ap);
                            ffma2(mhi[ii], vhi, ap);
                        }
                    }
#pragma unroll
                    for (int ii = 0; ii < 8; ii++) {
                        int r = bb * NC + half * 8 + ii;
                        float2 l = unpack2(mlo[ii]);
                        float2 h = unpack2(mhi[ii]);
                        __half2 h0 = __floats2half2_rn(l.x, l.y);
                        __half2 h1 = __floats2half2_rn(h.x, h.y);
                        uint2 st; st.x = *(uint32_t*)&h0; st.y = *(uint32_t*)&h1;
                        *(uint2*)(smem + OFF_M + r * WST + lane * 8) = st;
                    }
                }
            }
        }
        __syncthreads();

        // ---- GEMM: D[128,128] = M[128,128] x W[128,128]^T; warp -> 2 row-tiles x 32 cols ----
        {
            const int ct = w & 3;        // col tile (32 cols)
            const int rb = w >> 2;       // row block (32 rows = 2 tiles of 16)
            float d[2][4][4];
#pragma unroll
            for (int t = 0; t < 2; t++)
#pragma unroll
                for (int nt = 0; nt < 4; nt++)
#pragma unroll
                    for (int k = 0; k < 4; k++) d[t][nt][k] = 0.f;

            const uint32_t aBase0 = sb + OFF_M
                + (uint32_t)(rb * 32 + (lane & 15)) * WST + (uint32_t)((lane >> 4) * 16);
            const uint32_t aBase1 = aBase0 + 16 * WST;
            const uint32_t bBase0 = sb + OFF_W
                + (uint32_t)(ct * 32 + (lane & 7) + ((lane >> 4) * 8)) * WST
                + (uint32_t)(((lane >> 3) & 1) * 16);
            const uint32_t bBase1 = bBase0 + 16 * WST;

#pragma unroll
            for (int s = 0; s < 8; s++) {
                uint32_t a0f[4], a1f[4], b0r[4], b1r[4];
                ldsm_x4(a0f, aBase0 + s * 32);
                ldsm_x4(a1f, aBase1 + s * 32);
                ldsm_x4(b0r, bBase0 + s * 32);
                ldsm_x4(b1r, bBase1 + s * 32);
                mma16816(d[0][0], a0f, b0r + 0);
                mma16816(d[0][1], a0f, b0r + 2);
                mma16816(d[0][2], a0f, b1r + 0);
                mma16816(d[0][3], a0f, b1r + 2);
                mma16816(d[1][0], a1f, b0r + 0);
                mma16816(d[1][1], a1f, b0r + 2);
                mma16816(d[1][2], a1f, b1r + 0);
                mma16816(d[1][3], a1f, b1r + 2);
            }

            // ---- epilogue: bias + direct stores (guarded per batch) ----
            const int g = lane >> 2, t4 = lane & 3;
#pragma unroll
            for (int t = 0; t < 2; t++) {
                const int bidx = rb * 2 + t;       // batch index in round
                if (bidx < nb) {
                    float* ob = out + (size_t)(b0 + R * BPRD + bidx) * (NC * HID);
                    float* o0 = ob + g * HID;
                    float* o1 = ob + (g + 8) * HID;
#pragma unroll
                    for (int nt = 0; nt < 4; nt++) {
                        int col = ct * 32 + nt * 8 + 2 * t4;
                        float bv0 = s_bias[col], bv1 = s_bias[col + 1];
                        *(float2*)(o0 + col) = make_float2(d[t][nt][0] + bv0, d[t][nt][1] + bv1);
                        *(float2*)(o1 + col) = make_float2(d[t][nt][2] + bv0, d[t][nt][3] + bv1);
                    }
                }
            }
        }
        __syncthreads();   // M tile must be fully consumed before next round's pool overwrites it
    }
}

extern "C" void kernel_launch(void* const* d_in, const int* in_sizes, int n_in,
                              void* d_out, int out_size) {
    const int*   la   = (const int*)  d_in[0];   // (2048, 512) int32
    const float* adj  = (const float*)d_in[1];   // (16, 16) f32
    const float* qemb = (const float*)d_in[2];   // (513, 128) f32
    const float* W    = (const float*)d_in[3];   // (128, 128) f32
    const float* bias = (const float*)d_in[4];   // (128,) f32
    float* out = (float*)d_out;                  // (2048, 16, 128) f32

    cudaFuncSetAttribute(enc_kernel, cudaFuncAttributeMaxDynamicSharedMemorySize, SMEM_REQ);
    prep_kernel<<<322, 256>>>(adj, W, qemb);
    enc_kernel<<<GRID, THREADS, SMEM_REQ>>>(la, bias, out);
}